// round 1
// baseline (speedup 1.0000x reference)
#include <cuda_runtime.h>
#include <math.h>

// Problem constants
#define BB 2
#define TT 1024
#define DD 1024
#define HH 16
#define DH 64
#define MM 4096
#define VV 50257
#define LL 4
#define BT (BB*TT)          // 2048
#define BTD (BB*TT*DD)      // 2097152

// ---------------- scratch (device globals, no runtime alloc) ----------------
__device__ float g_h[BTD];
__device__ float g_ln[BTD];
__device__ float g_qkv[3*BTD];
__device__ float g_attn[BTD];
__device__ float g_mlp[BT*MM];

// ---------------- embedding ----------------
__global__ void embed_kernel(const int* __restrict__ x,
                             const float* __restrict__ tok,
                             const float* __restrict__ pos) {
    int i = blockIdx.x * blockDim.x + threadIdx.x;
    if (i >= BTD) return;
    int d  = i % DD;
    int bt = i / DD;
    int t  = bt % TT;
    g_h[i] = tok[(long)x[bt] * DD + d] + pos[t * DD + d];
}

// ---------------- layernorm (one block per row of D=1024) ----------------
__global__ void ln_kernel(const float* __restrict__ x,
                          const float* __restrict__ g,
                          const float* __restrict__ b,
                          float* __restrict__ y) {
    __shared__ float red[256];
    int row = blockIdx.x;
    const float* xr = x + (long)row * DD;
    float* yr = y + (long)row * DD;
    int tid = threadIdx.x;

    float s = 0.f;
    for (int i = tid; i < DD; i += 256) s += xr[i];
    red[tid] = s; __syncthreads();
    for (int st = 128; st > 0; st >>= 1) { if (tid < st) red[tid] += red[tid + st]; __syncthreads(); }
    float mu = red[0] * (1.0f / DD);
    __syncthreads();

    float v = 0.f;
    for (int i = tid; i < DD; i += 256) { float d = xr[i] - mu; v += d * d; }
    red[tid] = v; __syncthreads();
    for (int st = 128; st > 0; st >>= 1) { if (tid < st) red[tid] += red[tid + st]; __syncthreads(); }
    float rstd = rsqrtf(red[0] * (1.0f / DD) + 1e-5f);

    for (int i = tid; i < DD; i += 256)
        yr[i] = (xr[i] - mu) * rstd * g[i] + b[i];
}

// ---------------- SGEMM: C[M,N] = act(A[M,K] @ W[K,N] + bias) (+res) ----------------
// M % 128 == 0, K % 8 == 0 guaranteed; N guarded.
// act: 0 = none, 1 = exact GELU
__global__ __launch_bounds__(256)
void sgemm_kernel(const float* __restrict__ A, const float* __restrict__ W,
                  const float* __restrict__ bias, const float* __restrict__ res,
                  float* __restrict__ C, int M, int N, int K, int act) {
    __shared__ float As[8][128];
    __shared__ float Bs[8][128];

    int tid = threadIdx.x;
    int m0 = blockIdx.y * 128, n0 = blockIdx.x * 128;
    int tr = tid >> 4, tc = tid & 15;       // 16x16 threads, each 8x8 outputs

    float acc[8][8];
    #pragma unroll
    for (int i = 0; i < 8; i++)
        #pragma unroll
        for (int j = 0; j < 8; j++) acc[i][j] = 0.f;

    int arow = tid >> 1, acol = (tid & 1) * 4;   // A: 128 rows x 8 cols, float4
    int brow = tid >> 5, bcol = (tid & 31) * 4;  // B: 8 rows x 128 cols, scalar+guard

    for (int k0 = 0; k0 < K; k0 += 8) {
        float4 av = *reinterpret_cast<const float4*>(&A[(long)(m0 + arow) * K + k0 + acol]);
        As[acol + 0][arow] = av.x;
        As[acol + 1][arow] = av.y;
        As[acol + 2][arow] = av.z;
        As[acol + 3][arow] = av.w;

        const float* wrow = &W[(long)(k0 + brow) * N + n0 + bcol];
        #pragma unroll
        for (int j = 0; j < 4; j++) {
            int n = n0 + bcol + j;
            Bs[brow][bcol + j] = (n < N) ? wrow[j] : 0.f;
        }
        __syncthreads();

        #pragma unroll
        for (int k = 0; k < 8; k++) {
            float ar[8], br[8];
            float4 a0 = *reinterpret_cast<const float4*>(&As[k][tr * 8]);
            float4 a1 = *reinterpret_cast<const float4*>(&As[k][tr * 8 + 4]);
            ar[0]=a0.x; ar[1]=a0.y; ar[2]=a0.z; ar[3]=a0.w;
            ar[4]=a1.x; ar[5]=a1.y; ar[6]=a1.z; ar[7]=a1.w;
            float4 b0 = *reinterpret_cast<const float4*>(&Bs[k][tc * 8]);
            float4 b1 = *reinterpret_cast<const float4*>(&Bs[k][tc * 8 + 4]);
            br[0]=b0.x; br[1]=b0.y; br[2]=b0.z; br[3]=b0.w;
            br[4]=b1.x; br[5]=b1.y; br[6]=b1.z; br[7]=b1.w;
            #pragma unroll
            for (int i = 0; i < 8; i++)
                #pragma unroll
                for (int j = 0; j < 8; j++)
                    acc[i][j] += ar[i] * br[j];
        }
        __syncthreads();
    }

    #pragma unroll
    for (int i = 0; i < 8; i++) {
        int m = m0 + tr * 8 + i;
        #pragma unroll
        for (int j = 0; j < 8; j++) {
            int n = n0 + tc * 8 + j;
            if (n < N) {
                float v = acc[i][j] + (bias ? bias[n] : 0.f);
                if (act == 1) v = 0.5f * v * (1.0f + erff(v * 0.70710678118654752f));
                long idx = (long)m * N + n;
                if (res) v += res[idx];
                C[idx] = v;
            }
        }
    }
}

// ---------------- fused attention: one block per (b,h,s), full (non-causal) softmax ----------------
__global__ __launch_bounds__(128)
void attn_kernel(const float* __restrict__ qkv, float* __restrict__ out) {
    __shared__ float qs[DH];
    __shared__ float sc[TT];
    __shared__ float tile[128 * 65];
    __shared__ float red[128];

    int blk = blockIdx.x;
    int s  = blk % TT;
    int bh = blk / TT;
    int h  = bh % HH;
    int b  = bh / HH;

    const float* q = qkv;
    const float* k = qkv + BTD;
    const float* v = qkv + 2 * BTD;

    int tid = threadIdx.x;
    if (tid < DH) qs[tid] = q[((long)(b * TT + s)) * DD + h * DH + tid];
    __syncthreads();

    int c = tid & 63, r0 = tid >> 6;

    // scores
    for (int t0 = 0; t0 < TT; t0 += 128) {
        for (int r = r0; r < 128; r += 2)
            tile[r * 65 + c] = k[((long)(b * TT + t0 + r)) * DD + h * DH + c];
        __syncthreads();
        float dot = 0.f;
        #pragma unroll
        for (int d = 0; d < DH; d++) dot += qs[d] * tile[tid * 65 + d];
        sc[t0 + tid] = dot * 0.125f;
        __syncthreads();
    }

    // softmax over keys
    float m = -1e30f;
    for (int i = tid; i < TT; i += 128) m = fmaxf(m, sc[i]);
    red[tid] = m; __syncthreads();
    for (int st = 64; st > 0; st >>= 1) { if (tid < st) red[tid] = fmaxf(red[tid], red[tid + st]); __syncthreads(); }
    m = red[0]; __syncthreads();

    float sum = 0.f;
    for (int i = tid; i < TT; i += 128) { float e = expf(sc[i] - m); sc[i] = e; sum += e; }
    red[tid] = sum; __syncthreads();
    for (int st = 64; st > 0; st >>= 1) { if (tid < st) red[tid] += red[tid + st]; __syncthreads(); }
    float inv = 1.0f / red[0];
    __syncthreads();

    // alpha @ V
    float acc = 0.f;
    for (int t0 = 0; t0 < TT; t0 += 128) {
        for (int r = r0; r < 128; r += 2)
            tile[r * 65 + c] = v[((long)(b * TT + t0 + r)) * DD + h * DH + c];
        __syncthreads();
        for (int r = r0; r < 128; r += 2)
            acc += sc[t0 + r] * tile[r * 65 + c];
        __syncthreads();
    }
    red[tid] = acc; __syncthreads();
    if (tid < 64)
        out[((long)(b * TT + s)) * DD + h * DH + tid] = (red[tid] + red[tid + 64]) * inv;
}

// ---------------- host orchestration ----------------
static inline void run_gemm(const float* A, const float* W, const float* bias,
                            const float* res, float* C, int M, int N, int K, int act) {
    dim3 grid((N + 127) / 128, (M + 127) / 128);
    sgemm_kernel<<<grid, 256>>>(A, W, bias, res, C, M, N, K, act);
}

extern "C" void kernel_launch(void* const* d_in, const int* in_sizes, int n_in,
                              void* d_out, int out_size) {
    const int*   x       = (const int*)  d_in[0];
    const float* tok_emb = (const float*)d_in[1];
    const float* pos_emb = (const float*)d_in[2];
    const float* ln1_g   = (const float*)d_in[3];
    const float* ln1_b   = (const float*)d_in[4];
    const float* qkv_w   = (const float*)d_in[5];
    const float* qkv_b   = (const float*)d_in[6];
    const float* out_w   = (const float*)d_in[7];
    const float* out_b   = (const float*)d_in[8];
    const float* ln2_g   = (const float*)d_in[9];
    const float* ln2_b   = (const float*)d_in[10];
    const float* wi_w    = (const float*)d_in[11];
    const float* wi_b    = (const float*)d_in[12];
    const float* wo_w    = (const float*)d_in[13];
    const float* wo_b    = (const float*)d_in[14];
    const float* ln_g    = (const float*)d_in[15];
    const float* ln_b    = (const float*)d_in[16];
    const float* head_w  = (const float*)d_in[17];
    const float* head_b  = (const float*)d_in[18];
    float* logits = (float*)d_out;

    float *h, *ln, *qkv, *attn, *mlp;
    cudaGetSymbolAddress((void**)&h,    g_h);
    cudaGetSymbolAddress((void**)&ln,   g_ln);
    cudaGetSymbolAddress((void**)&qkv,  g_qkv);
    cudaGetSymbolAddress((void**)&attn, g_attn);
    cudaGetSymbolAddress((void**)&mlp,  g_mlp);

    // embedding
    embed_kernel<<<(BTD + 255) / 256, 256>>>(x, tok_emb, pos_emb);

    for (int l = 0; l < LL; l++) {
        // attn block
        ln_kernel<<<BT, 256>>>(h, ln1_g + l * DD, ln1_b + l * DD, ln);
        run_gemm(ln, qkv_w + (long)l * DD * 3 * DD, qkv_b + l * 3 * DD,
                 nullptr, qkv, BT, 3 * DD, DD, 0);
        attn_kernel<<<BB * HH * TT, 128>>>(qkv, attn);
        run_gemm(attn, out_w + (long)l * DD * DD, out_b + l * DD,
                 h, h, BT, DD, DD, 0);   // h = h + attn@W + b

        // mlp block
        ln_kernel<<<BT, 256>>>(h, ln2_g + l * DD, ln2_b + l * DD, ln);
        run_gemm(ln, wi_w + (long)l * DD * MM, wi_b + l * MM,
                 nullptr, mlp, BT, MM, DD, 1);   // GELU
        run_gemm(mlp, wo_w + (long)l * MM * DD, wo_b + l * DD,
                 h, h, BT, DD, MM, 0);   // h = h + mlp@W + b
    }

    // final LN + head
    ln_kernel<<<BT, 256>>>(h, ln_g, ln_b, ln);
    run_gemm(ln, head_w, head_b, nullptr, logits, BT, VV, DD, 0);
}

// round 3
// speedup vs baseline: 1.3955x; 1.3955x over previous
#include <cuda_runtime.h>
#include <cuda_bf16.h>
#include <math.h>
#include <stdint.h>

// Problem constants
#define BB 2
#define TT 1024
#define DD 1024
#define HH 16
#define DH 64
#define MM 4096
#define VV 50257
#define LL 4
#define BT (BB*TT)          // 2048
#define BTD (BB*TT*DD)      // 2097152

// ---------------- scratch (device globals, no runtime alloc) ----------------
__device__ float g_h[BTD];
__device__ float g_ln[BTD];
__device__ float g_qkv[3*BTD];
__device__ float g_attn[BTD];
__device__ float g_mlp[BT*MM];

// ---------------- embedding ----------------
__global__ void embed_kernel(const int* __restrict__ x,
                             const float* __restrict__ tok,
                             const float* __restrict__ pos) {
    int i = blockIdx.x * blockDim.x + threadIdx.x;
    if (i >= BTD) return;
    int d  = i % DD;
    int bt = i / DD;
    int t  = bt % TT;
    g_h[i] = tok[(long)x[bt] * DD + d] + pos[t * DD + d];
}

// ---------------- layernorm (one block per row of D=1024) ----------------
__global__ void ln_kernel(const float* __restrict__ x,
                          const float* __restrict__ g,
                          const float* __restrict__ b,
                          float* __restrict__ y) {
    __shared__ float red[256];
    int row = blockIdx.x;
    const float* xr = x + (long)row * DD;
    float* yr = y + (long)row * DD;
    int tid = threadIdx.x;

    float s = 0.f;
    for (int i = tid; i < DD; i += 256) s += xr[i];
    red[tid] = s; __syncthreads();
    for (int st = 128; st > 0; st >>= 1) { if (tid < st) red[tid] += red[tid + st]; __syncthreads(); }
    float mu = red[0] * (1.0f / DD);
    __syncthreads();

    float v = 0.f;
    for (int i = tid; i < DD; i += 256) { float d = xr[i] - mu; v += d * d; }
    red[tid] = v; __syncthreads();
    for (int st = 128; st > 0; st >>= 1) { if (tid < st) red[tid] += red[tid + st]; __syncthreads(); }
    float rstd = rsqrtf(red[0] * (1.0f / DD) + 1e-5f);

    for (int i = tid; i < DD; i += 256)
        yr[i] = (xr[i] - mu) * rstd * g[i] + b[i];
}

// ---------------- tensor-core helpers ----------------
__device__ __forceinline__ uint32_t smem_u32(const void* p) {
    return (uint32_t)__cvta_generic_to_shared(p);
}
__device__ __forceinline__ void ldsm_x4(uint32_t& r0, uint32_t& r1, uint32_t& r2, uint32_t& r3, uint32_t a) {
    asm volatile("ldmatrix.sync.aligned.m8n8.x4.shared.b16 {%0,%1,%2,%3}, [%4];\n"
                 : "=r"(r0), "=r"(r1), "=r"(r2), "=r"(r3) : "r"(a));
}
__device__ __forceinline__ void ldsm_x4_t(uint32_t& r0, uint32_t& r1, uint32_t& r2, uint32_t& r3, uint32_t a) {
    asm volatile("ldmatrix.sync.aligned.m8n8.x4.trans.shared.b16 {%0,%1,%2,%3}, [%4];\n"
                 : "=r"(r0), "=r"(r1), "=r"(r2), "=r"(r3) : "r"(a));
}
__device__ __forceinline__ void mma_bf16(float* c,
        uint32_t a0, uint32_t a1, uint32_t a2, uint32_t a3,
        uint32_t b0, uint32_t b1) {
    asm volatile("mma.sync.aligned.m16n8k16.row.col.f32.bf16.bf16.f32 "
                 "{%0,%1,%2,%3}, {%4,%5,%6,%7}, {%8,%9}, {%0,%1,%2,%3};\n"
                 : "+f"(c[0]), "+f"(c[1]), "+f"(c[2]), "+f"(c[3])
                 : "r"(a0), "r"(a1), "r"(a2), "r"(a3), "r"(b0), "r"(b1));
}

// split f into hi/lo bf16
__device__ __forceinline__ void split_bf16(float f, __nv_bfloat16& h, __nv_bfloat16& l) {
    h = __float2bfloat16(f);
    l = __float2bfloat16(f - __bfloat162float(h));
}

// ---------------- GEMM (bf16x3 tensor core): C[M,N] = act(A[M,K]@W[K,N]+bias)(+res) ----------------
// tile 128x128x32, 256 threads, warps 4(m) x 2(n), warp tile 32x64
#define AKS 40    // A smem k-stride (32 + 8 pad), 80B rows
#define BNS 136   // B smem n-stride (128 + 8 pad), 272B rows

__global__ __launch_bounds__(256)
void gemm_tc(const float* __restrict__ A, const float* __restrict__ W,
             const float* __restrict__ bias, const float* __restrict__ res,
             float* __restrict__ C, int M, int N, int K, int act)
{
    __shared__ __align__(16) __nv_bfloat16 Ah[128][AKS];
    __shared__ __align__(16) __nv_bfloat16 Al[128][AKS];
    __shared__ __align__(16) __nv_bfloat16 Bh[32][BNS];
    __shared__ __align__(16) __nv_bfloat16 Bl[32][BNS];

    int tid  = threadIdx.x;
    int m0   = blockIdx.x * 128;   // x = M so concurrent blocks share W tiles in L2
    int n0   = blockIdx.y * 128;
    int warp = tid >> 5, lane = tid & 31;
    int wm0  = (warp >> 1) * 32;
    int wn0  = (warp & 1) * 64;
    int gid  = lane >> 2, tig = lane & 3;

    float acc[2][8][4];
    #pragma unroll
    for (int i = 0; i < 2; i++)
        #pragma unroll
        for (int j = 0; j < 8; j++)
            #pragma unroll
            for (int q = 0; q < 4; q++) acc[i][j][q] = 0.f;

    // gmem load assignments
    int arow = tid >> 1;            // 2 threads per A row, 16 floats each
    int ak   = (tid & 1) * 16;
    int brow = tid >> 3;            // vector path: 8 threads per B k-row, 16 floats each
    int bn   = (tid & 7) * 16;
    // float4 on W is only legal if every W row base is 16B aligned => N % 4 == 0
    bool bvec = ((N & 3) == 0) && (n0 + 128 <= N);

    for (int k0 = 0; k0 < K; k0 += 32) {
        // ---- load + convert A tile ----
        {
            const float* ap = A + (long)(m0 + arow) * K + k0 + ak;
            #pragma unroll
            for (int q = 0; q < 4; q++) {
                float4 v = *reinterpret_cast<const float4*>(ap + q * 4);
                float f[4] = {v.x, v.y, v.z, v.w};
                #pragma unroll
                for (int j = 0; j < 4; j += 2) {
                    __nv_bfloat16 h0, l0, h1, l1;
                    split_bf16(f[j], h0, l0);
                    split_bf16(f[j+1], h1, l1);
                    int kc = ak + q * 4 + j;
                    *reinterpret_cast<__nv_bfloat162*>(&Ah[arow][kc]) = __nv_bfloat162(h0, h1);
                    *reinterpret_cast<__nv_bfloat162*>(&Al[arow][kc]) = __nv_bfloat162(l0, l1);
                }
            }
        }
        // ---- load + convert B tile ----
        if (bvec) {
            const float* wp = W + (long)(k0 + brow) * N + n0 + bn;
            #pragma unroll
            for (int q = 0; q < 4; q++) {
                float4 v = *reinterpret_cast<const float4*>(wp + q * 4);
                float f[4] = {v.x, v.y, v.z, v.w};
                #pragma unroll
                for (int j = 0; j < 4; j += 2) {
                    __nv_bfloat16 h0, l0, h1, l1;
                    split_bf16(f[j], h0, l0);
                    split_bf16(f[j+1], h1, l1);
                    int nc = bn + q * 4 + j;
                    *reinterpret_cast<__nv_bfloat162*>(&Bh[brow][nc]) = __nv_bfloat162(h0, h1);
                    *reinterpret_cast<__nv_bfloat162*>(&Bl[brow][nc]) = __nv_bfloat162(l0, l1);
                }
            }
        } else {
            // coalesced scalar path: consecutive tids -> consecutive columns
            #pragma unroll
            for (int pass = 0; pass < 16; pass++) {
                int idx = pass * 256 + tid;
                int row = idx >> 7;          // 0..31
                int col = idx & 127;         // 0..127
                int n = n0 + col;
                float f = (n < N) ? W[(long)(k0 + row) * N + n] : 0.f;
                __nv_bfloat16 h, l;
                split_bf16(f, h, l);
                Bh[row][col] = h;
                Bl[row][col] = l;
            }
        }
        __syncthreads();

        #pragma unroll
        for (int kk = 0; kk < 32; kk += 16) {
            uint32_t ah[2][4], al[2][4], bh[8][2], bl[8][2];
            #pragma unroll
            for (int mc = 0; mc < 2; mc++) {
                int r = wm0 + mc * 16 + (lane & 15);
                int c = kk + ((lane >> 4) << 3);
                ldsm_x4(ah[mc][0], ah[mc][1], ah[mc][2], ah[mc][3], smem_u32(&Ah[r][c]));
                ldsm_x4(al[mc][0], al[mc][1], al[mc][2], al[mc][3], smem_u32(&Al[r][c]));
            }
            #pragma unroll
            for (int pc = 0; pc < 4; pc++) {
                int r = kk + (lane & 15);
                int c = wn0 + pc * 16 + ((lane >> 4) << 3);
                ldsm_x4_t(bh[2*pc][0], bh[2*pc][1], bh[2*pc+1][0], bh[2*pc+1][1], smem_u32(&Bh[r][c]));
                ldsm_x4_t(bl[2*pc][0], bl[2*pc][1], bl[2*pc+1][0], bl[2*pc+1][1], smem_u32(&Bl[r][c]));
            }
            #pragma unroll
            for (int mc = 0; mc < 2; mc++)
                #pragma unroll
                for (int ch = 0; ch < 8; ch++) {
                    mma_bf16(acc[mc][ch], ah[mc][0], ah[mc][1], ah[mc][2], ah[mc][3], bh[ch][0], bh[ch][1]);
                    mma_bf16(acc[mc][ch], ah[mc][0], ah[mc][1], ah[mc][2], ah[mc][3], bl[ch][0], bl[ch][1]);
                    mma_bf16(acc[mc][ch], al[mc][0], al[mc][1], al[mc][2], al[mc][3], bh[ch][0], bh[ch][1]);
                }
        }
        __syncthreads();
    }

    // ---- epilogue ----
    #pragma unroll
    for (int mc = 0; mc < 2; mc++) {
        #pragma unroll
        for (int ch = 0; ch < 8; ch++) {
            int n = n0 + wn0 + (ch >> 1) * 16 + (ch & 1) * 8 + tig * 2;
            #pragma unroll
            for (int h2 = 0; h2 < 2; h2++) {
                int m = m0 + wm0 + mc * 16 + gid + h2 * 8;
                #pragma unroll
                for (int j = 0; j < 2; j++) {
                    int nn = n + j;
                    if (nn < N) {
                        float v = acc[mc][ch][h2 * 2 + j] + bias[nn];
                        if (act == 1) v = 0.5f * v * (1.0f + erff(v * 0.70710678118654752f));
                        long idx = (long)m * N + nn;
                        if (res) v += res[idx];
                        C[idx] = v;
                    }
                }
            }
        }
    }
}

// ---------------- fused attention: one block per (b,h,s), full (non-causal) softmax ----------------
__global__ __launch_bounds__(128)
void attn_kernel(const float* __restrict__ qkv, float* __restrict__ out) {
    __shared__ float qs[DH];
    __shared__ float sc[TT];
    __shared__ float tile[128 * 65];
    __shared__ float red[128];

    int blk = blockIdx.x;
    int s  = blk % TT;
    int bh = blk / TT;
    int h  = bh % HH;
    int b  = bh / HH;

    const float* q = qkv;
    const float* k = qkv + BTD;
    const float* v = qkv + 2 * BTD;

    int tid = threadIdx.x;
    if (tid < DH) qs[tid] = q[((long)(b * TT + s)) * DD + h * DH + tid];
    __syncthreads();

    int c = tid & 63, r0 = tid >> 6;

    // scores
    for (int t0 = 0; t0 < TT; t0 += 128) {
        for (int r = r0; r < 128; r += 2)
            tile[r * 65 + c] = k[((long)(b * TT + t0 + r)) * DD + h * DH + c];
        __syncthreads();
        float dot = 0.f;
        #pragma unroll
        for (int d = 0; d < DH; d++) dot += qs[d] * tile[tid * 65 + d];
        sc[t0 + tid] = dot * 0.125f;
        __syncthreads();
    }

    // softmax over keys
    float m = -1e30f;
    for (int i = tid; i < TT; i += 128) m = fmaxf(m, sc[i]);
    red[tid] = m; __syncthreads();
    for (int st = 64; st > 0; st >>= 1) { if (tid < st) red[tid] = fmaxf(red[tid], red[tid + st]); __syncthreads(); }
    m = red[0]; __syncthreads();

    float sum = 0.f;
    for (int i = tid; i < TT; i += 128) { float e = expf(sc[i] - m); sc[i] = e; sum += e; }
    red[tid] = sum; __syncthreads();
    for (int st = 64; st > 0; st >>= 1) { if (tid < st) red[tid] += red[tid + st]; __syncthreads(); }
    float inv = 1.0f / red[0];
    __syncthreads();

    // alpha @ V
    float acc = 0.f;
    for (int t0 = 0; t0 < TT; t0 += 128) {
        for (int r = r0; r < 128; r += 2)
            tile[r * 65 + c] = v[((long)(b * TT + t0 + r)) * DD + h * DH + c];
        __syncthreads();
        for (int r = r0; r < 128; r += 2)
            acc += sc[t0 + r] * tile[r * 65 + c];
        __syncthreads();
    }
    red[tid] = acc; __syncthreads();
    if (tid < 64)
        out[((long)(b * TT + s)) * DD + h * DH + tid] = (red[tid] + red[tid + 64]) * inv;
}

// ---------------- host orchestration ----------------
static inline void run_gemm(const float* A, const float* W, const float* bias,
                            const float* res, float* C, int M, int N, int K, int act) {
    dim3 grid(M / 128, (N + 127) / 128);
    gemm_tc<<<grid, 256>>>(A, W, bias, res, C, M, N, K, act);
}

extern "C" void kernel_launch(void* const* d_in, const int* in_sizes, int n_in,
                              void* d_out, int out_size) {
    const int*   x       = (const int*)  d_in[0];
    const float* tok_emb = (const float*)d_in[1];
    const float* pos_emb = (const float*)d_in[2];
    const float* ln1_g   = (const float*)d_in[3];
    const float* ln1_b   = (const float*)d_in[4];
    const float* qkv_w   = (const float*)d_in[5];
    const float* qkv_b   = (const float*)d_in[6];
    const float* out_w   = (const float*)d_in[7];
    const float* out_b   = (const float*)d_in[8];
    const float* ln2_g   = (const float*)d_in[9];
    const float* ln2_b   = (const float*)d_in[10];
    const float* wi_w    = (const float*)d_in[11];
    const float* wi_b    = (const float*)d_in[12];
    const float* wo_w    = (const float*)d_in[13];
    const float* wo_b    = (const float*)d_in[14];
    const float* ln_g    = (const float*)d_in[15];
    const float* ln_b    = (const float*)d_in[16];
    const float* head_w  = (const float*)d_in[17];
    const float* head_b  = (const float*)d_in[18];
    float* logits = (float*)d_out;

    float *h, *ln, *qkv, *attn, *mlp;
    cudaGetSymbolAddress((void**)&h,    g_h);
    cudaGetSymbolAddress((void**)&ln,   g_ln);
    cudaGetSymbolAddress((void**)&qkv,  g_qkv);
    cudaGetSymbolAddress((void**)&attn, g_attn);
    cudaGetSymbolAddress((void**)&mlp,  g_mlp);

    // embedding
    embed_kernel<<<(BTD + 255) / 256, 256>>>(x, tok_emb, pos_emb);

    for (int l = 0; l < LL; l++) {
        // attn block
        ln_kernel<<<BT, 256>>>(h, ln1_g + l * DD, ln1_b + l * DD, ln);
        run_gemm(ln, qkv_w + (long)l * DD * 3 * DD, qkv_b + l * 3 * DD,
                 nullptr, qkv, BT, 3 * DD, DD, 0);
        attn_kernel<<<BB * HH * TT, 128>>>(qkv, attn);
        run_gemm(attn, out_w + (long)l * DD * DD, out_b + l * DD,
                 h, h, BT, DD, DD, 0);   // h = h + attn@W + b

        // mlp block
        ln_kernel<<<BT, 256>>>(h, ln2_g + l * DD, ln2_b + l * DD, ln);
        run_gemm(ln, wi_w + (long)l * DD * MM, wi_b + l * MM,
                 nullptr, mlp, BT, MM, DD, 1);   // GELU
        run_gemm(mlp, wo_w + (long)l * MM * DD, wo_b + l * DD,
                 h, h, BT, DD, MM, 0);   // h = h + mlp@W + b
    }

    // final LN + head
    ln_kernel<<<BT, 256>>>(h, ln_g, ln_b, ln);
    run_gemm(ln, head_w, head_b, nullptr, logits, BT, VV, DD, 0);
}

// round 4
// speedup vs baseline: 1.5130x; 1.0842x over previous
#include <cuda_runtime.h>
#include <cuda_bf16.h>
#include <math.h>
#include <stdint.h>

// Problem constants
#define BB 2
#define TT 1024
#define DD 1024
#define HH 16
#define DH 64
#define MM 4096
#define VV 50257
#define VP 50304           // VV padded to multiple of 128
#define LL 4
#define BT (BB*TT)          // 2048
#define BTD (BB*TT*DD)      // 2097152

// ---------------- scratch (device globals, no runtime alloc) ----------------
__device__ float g_h[BTD];
__device__ float g_qkv[3*BTD];

__device__ __nv_bfloat16 g_lnh[BTD],  g_lnl[BTD];
__device__ __nv_bfloat16 g_ath[BTD],  g_atl[BTD];
__device__ __nv_bfloat16 g_mlph[(long)BT*MM], g_mlpl[(long)BT*MM];

// split weights (hi/lo)
__device__ __nv_bfloat16 g_qkvwh[(long)LL*DD*3*DD], g_qkvwl[(long)LL*DD*3*DD];
__device__ __nv_bfloat16 g_outwh[(long)LL*DD*DD],   g_outwl[(long)LL*DD*DD];
__device__ __nv_bfloat16 g_wiwh[(long)LL*DD*MM],    g_wiwl[(long)LL*DD*MM];
__device__ __nv_bfloat16 g_wowh[(long)LL*MM*DD],    g_wowl[(long)LL*MM*DD];
__device__ __nv_bfloat16 g_headwh[(long)DD*VP],     g_headwl[(long)DD*VP];

// ---------------- helpers ----------------
__device__ __forceinline__ uint32_t smem_u32(const void* p) {
    return (uint32_t)__cvta_generic_to_shared(p);
}
__device__ __forceinline__ void cp16(void* dst, const void* src) {
    asm volatile("cp.async.ca.shared.global [%0], [%1], 16;\n"
                 :: "r"(smem_u32(dst)), "l"(src));
}
__device__ __forceinline__ void cp_commit() { asm volatile("cp.async.commit_group;\n"); }
__device__ __forceinline__ void cp_wait0()  { asm volatile("cp.async.wait_group 0;\n"); }
__device__ __forceinline__ void cp_wait1()  { asm volatile("cp.async.wait_group 1;\n"); }

__device__ __forceinline__ void ldsm_x4(uint32_t& r0, uint32_t& r1, uint32_t& r2, uint32_t& r3, uint32_t a) {
    asm volatile("ldmatrix.sync.aligned.m8n8.x4.shared.b16 {%0,%1,%2,%3}, [%4];\n"
                 : "=r"(r0), "=r"(r1), "=r"(r2), "=r"(r3) : "r"(a));
}
__device__ __forceinline__ void ldsm_x4_t(uint32_t& r0, uint32_t& r1, uint32_t& r2, uint32_t& r3, uint32_t a) {
    asm volatile("ldmatrix.sync.aligned.m8n8.x4.trans.shared.b16 {%0,%1,%2,%3}, [%4];\n"
                 : "=r"(r0), "=r"(r1), "=r"(r2), "=r"(r3) : "r"(a));
}
__device__ __forceinline__ void mma_bf16(float* c,
        uint32_t a0, uint32_t a1, uint32_t a2, uint32_t a3,
        uint32_t b0, uint32_t b1) {
    asm volatile("mma.sync.aligned.m16n8k16.row.col.f32.bf16.bf16.f32 "
                 "{%0,%1,%2,%3}, {%4,%5,%6,%7}, {%8,%9}, {%0,%1,%2,%3};\n"
                 : "+f"(c[0]), "+f"(c[1]), "+f"(c[2]), "+f"(c[3])
                 : "r"(a0), "r"(a1), "r"(a2), "r"(a3), "r"(b0), "r"(b1));
}
__device__ __forceinline__ void split_bf16(float f, __nv_bfloat16& h, __nv_bfloat16& l) {
    h = __float2bfloat16(f);
    l = __float2bfloat16(f - __bfloat162float(h));
}

// ---------------- weight splitter: rows x Ncols fp32 -> hi/lo bf16, stride Ws (>=N, zero pad) ----------------
__global__ void split_w_kernel(const float* __restrict__ W,
                               __nv_bfloat16* __restrict__ Wh,
                               __nv_bfloat16* __restrict__ Wl,
                               long rows, long N, long Ws) {
    long total = rows * Ws;
    for (long i = (long)blockIdx.x * blockDim.x + threadIdx.x; i < total;
         i += (long)gridDim.x * blockDim.x) {
        long r = i / Ws, c = i - r * Ws;
        float f = (c < N) ? W[r * N + c] : 0.f;
        __nv_bfloat16 h, l;
        split_bf16(f, h, l);
        Wh[i] = h; Wl[i] = l;
    }
}

// ---------------- embedding ----------------
__global__ void embed_kernel(const int* __restrict__ x,
                             const float* __restrict__ tok,
                             const float* __restrict__ pos) {
    int i = blockIdx.x * blockDim.x + threadIdx.x;
    if (i >= BTD) return;
    int d  = i % DD;
    int bt = i / DD;
    int t  = bt % TT;
    g_h[i] = tok[(long)x[bt] * DD + d] + pos[t * DD + d];
}

// ---------------- layernorm -> bf16 hi/lo ----------------
__global__ void ln_kernel(const float* __restrict__ x,
                          const float* __restrict__ g,
                          const float* __restrict__ b,
                          __nv_bfloat16* __restrict__ yh,
                          __nv_bfloat16* __restrict__ yl) {
    __shared__ float red[256];
    int row = blockIdx.x;
    const float* xr = x + (long)row * DD;
    int tid = threadIdx.x;

    float s = 0.f;
    for (int i = tid; i < DD; i += 256) s += xr[i];
    red[tid] = s; __syncthreads();
    for (int st = 128; st > 0; st >>= 1) { if (tid < st) red[tid] += red[tid + st]; __syncthreads(); }
    float mu = red[0] * (1.0f / DD);
    __syncthreads();

    float v = 0.f;
    for (int i = tid; i < DD; i += 256) { float d = xr[i] - mu; v += d * d; }
    red[tid] = v; __syncthreads();
    for (int st = 128; st > 0; st >>= 1) { if (tid < st) red[tid] += red[tid + st]; __syncthreads(); }
    float rstd = rsqrtf(red[0] * (1.0f / DD) + 1e-5f);

    for (int i = tid; i < DD; i += 256) {
        float y = (xr[i] - mu) * rstd * g[i] + b[i];
        __nv_bfloat16 h, l;
        split_bf16(y, h, l);
        long idx = (long)row * DD + i;
        yh[idx] = h; yl[idx] = l;
    }
}

// ---------------- GEMM (bf16x3, pre-split operands, cp.async double buffer) ----------------
// tile 128x128x32, 256 threads, warps 4(m) x 2(n)
#define AKS 40      // A k-stride (32+8), 80B rows
#define BNS 136     // B n-stride (128+8), 272B rows
#define STG_A (128*AKS)             // 5120
#define STG_B (32*BNS)              // 4352
#define STG_ELEMS (2*STG_A + 2*STG_B)   // 18944 bf16 per stage
#define SMEM_BYTES (2 * STG_ELEMS * 2)  // 75776 bytes

struct Stage {
    __nv_bfloat16 *Ah, *Al, *Bh, *Bl;
};
__device__ __forceinline__ Stage stage_ptrs(__nv_bfloat16* smem, int st) {
    __nv_bfloat16* base = smem + st * STG_ELEMS;
    Stage s;
    s.Ah = base;
    s.Al = base + STG_A;
    s.Bh = base + 2 * STG_A;
    s.Bl = base + 2 * STG_A + STG_B;
    return s;
}

__device__ __forceinline__ void load_stage(Stage s, int tid,
        const __nv_bfloat16* __restrict__ Agh, const __nv_bfloat16* __restrict__ Agl,
        const __nv_bfloat16* __restrict__ Wh,  const __nv_bfloat16* __restrict__ Wl,
        int m0, int n0, int k0, int K, int Ws) {
    #pragma unroll
    for (int p = 0; p < 2; p++) {
        int idx = p * 256 + tid;
        int ar = idx >> 2, ac = (idx & 3) * 8;
        long aoff = (long)(m0 + ar) * K + k0 + ac;
        cp16(&s.Ah[ar * AKS + ac], Agh + aoff);
        cp16(&s.Al[ar * AKS + ac], Agl + aoff);
        int br = idx >> 4, bc = (idx & 15) * 8;
        long boff = (long)(k0 + br) * Ws + n0 + bc;
        cp16(&s.Bh[br * BNS + bc], Wh + boff);
        cp16(&s.Bl[br * BNS + bc], Wl + boff);
    }
}

// epilogue behavior: Cf (fp32 out, may be null), res (fp32 residual, may be null),
// Csh/Csl (bf16 split out, may be null), act 1 = exact GELU
__global__ __launch_bounds__(256)
void gemm_tc(const __nv_bfloat16* __restrict__ Agh, const __nv_bfloat16* __restrict__ Agl,
             const __nv_bfloat16* __restrict__ Wh,  const __nv_bfloat16* __restrict__ Wl,
             const float* __restrict__ bias, const float* __restrict__ res,
             float* __restrict__ Cf,
             __nv_bfloat16* __restrict__ Csh, __nv_bfloat16* __restrict__ Csl,
             int M, int N, int Ws, int K, int act)
{
    extern __shared__ __nv_bfloat16 smem[];

    int tid  = threadIdx.x;
    int m0   = blockIdx.x * 128;   // x = M so concurrent blocks share W tiles in L2
    int n0   = blockIdx.y * 128;
    int warp = tid >> 5, lane = tid & 31;
    int wm0  = (warp >> 1) * 32;
    int wn0  = (warp & 1) * 64;
    int gid  = lane >> 2, tig = lane & 3;

    float acc[2][8][4];
    #pragma unroll
    for (int i = 0; i < 2; i++)
        #pragma unroll
        for (int j = 0; j < 8; j++)
            #pragma unroll
            for (int q = 0; q < 4; q++) acc[i][j][q] = 0.f;

    int nkt = K >> 5;

    load_stage(stage_ptrs(smem, 0), tid, Agh, Agl, Wh, Wl, m0, n0, 0, K, Ws);
    cp_commit();

    for (int kt = 0; kt < nkt; kt++) {
        if (kt + 1 < nkt) {
            load_stage(stage_ptrs(smem, (kt + 1) & 1), tid, Agh, Agl, Wh, Wl,
                       m0, n0, (kt + 1) << 5, K, Ws);
            cp_commit();
            cp_wait1();
        } else {
            cp_wait0();
        }
        __syncthreads();

        Stage s = stage_ptrs(smem, kt & 1);
        #pragma unroll
        for (int kk = 0; kk < 32; kk += 16) {
            uint32_t ah[2][4], al[2][4], bh[8][2], bl[8][2];
            #pragma unroll
            for (int mc = 0; mc < 2; mc++) {
                int r = wm0 + mc * 16 + (lane & 15);
                int c = kk + ((lane >> 4) << 3);
                ldsm_x4(ah[mc][0], ah[mc][1], ah[mc][2], ah[mc][3], smem_u32(&s.Ah[r * AKS + c]));
                ldsm_x4(al[mc][0], al[mc][1], al[mc][2], al[mc][3], smem_u32(&s.Al[r * AKS + c]));
            }
            #pragma unroll
            for (int pc = 0; pc < 4; pc++) {
                int r = kk + (lane & 15);
                int c = wn0 + pc * 16 + ((lane >> 4) << 3);
                ldsm_x4_t(bh[2*pc][0], bh[2*pc][1], bh[2*pc+1][0], bh[2*pc+1][1], smem_u32(&s.Bh[r * BNS + c]));
                ldsm_x4_t(bl[2*pc][0], bl[2*pc][1], bl[2*pc+1][0], bl[2*pc+1][1], smem_u32(&s.Bl[r * BNS + c]));
            }
            #pragma unroll
            for (int mc = 0; mc < 2; mc++)
                #pragma unroll
                for (int ch = 0; ch < 8; ch++) {
                    mma_bf16(acc[mc][ch], ah[mc][0], ah[mc][1], ah[mc][2], ah[mc][3], bh[ch][0], bh[ch][1]);
                    mma_bf16(acc[mc][ch], ah[mc][0], ah[mc][1], ah[mc][2], ah[mc][3], bl[ch][0], bl[ch][1]);
                    mma_bf16(acc[mc][ch], al[mc][0], al[mc][1], al[mc][2], al[mc][3], bh[ch][0], bh[ch][1]);
                }
        }
        __syncthreads();
    }

    // ---- epilogue ----
    #pragma unroll
    for (int mc = 0; mc < 2; mc++) {
        #pragma unroll
        for (int ch = 0; ch < 8; ch++) {
            int n = n0 + wn0 + (ch >> 1) * 16 + (ch & 1) * 8 + tig * 2;
            #pragma unroll
            for (int h2 = 0; h2 < 2; h2++) {
                int m = m0 + wm0 + mc * 16 + gid + h2 * 8;
                #pragma unroll
                for (int j = 0; j < 2; j++) {
                    int nn = n + j;
                    if (nn < N) {
                        float v = acc[mc][ch][h2 * 2 + j] + bias[nn];
                        if (act == 1) v = 0.5f * v * (1.0f + erff(v * 0.70710678118654752f));
                        long idx = (long)m * N + nn;
                        if (res) v += res[idx];
                        if (Cf) Cf[idx] = v;
                        if (Csh) {
                            __nv_bfloat16 hh, ll;
                            split_bf16(v, hh, ll);
                            Csh[idx] = hh; Csl[idx] = ll;
                        }
                    }
                }
            }
        }
    }
}

// ---------------- fused attention: one block per (b,h,s); bf16 hi/lo output ----------------
__global__ __launch_bounds__(128)
void attn_kernel(const float* __restrict__ qkv,
                 __nv_bfloat16* __restrict__ oh, __nv_bfloat16* __restrict__ ol) {
    __shared__ float qs[DH];
    __shared__ float sc[TT];
    __shared__ float tile[128 * 65];
    __shared__ float red[128];

    int blk = blockIdx.x;
    int s  = blk % TT;
    int bh = blk / TT;
    int h  = bh % HH;
    int b  = bh / HH;

    const float* q = qkv;
    const float* k = qkv + BTD;
    const float* v = qkv + 2 * BTD;

    int tid = threadIdx.x;
    if (tid < DH) qs[tid] = q[((long)(b * TT + s)) * DD + h * DH + tid];
    __syncthreads();

    int c = tid & 63, r0 = tid >> 6;

    for (int t0 = 0; t0 < TT; t0 += 128) {
        for (int r = r0; r < 128; r += 2)
            tile[r * 65 + c] = k[((long)(b * TT + t0 + r)) * DD + h * DH + c];
        __syncthreads();
        float dot = 0.f;
        #pragma unroll
        for (int d = 0; d < DH; d++) dot += qs[d] * tile[tid * 65 + d];
        sc[t0 + tid] = dot * 0.125f;
        __syncthreads();
    }

    float m = -1e30f;
    for (int i = tid; i < TT; i += 128) m = fmaxf(m, sc[i]);
    red[tid] = m; __syncthreads();
    for (int st = 64; st > 0; st >>= 1) { if (tid < st) red[tid] = fmaxf(red[tid], red[tid + st]); __syncthreads(); }
    m = red[0]; __syncthreads();

    float sum = 0.f;
    for (int i = tid; i < TT; i += 128) { float e = expf(sc[i] - m); sc[i] = e; sum += e; }
    red[tid] = sum; __syncthreads();
    for (int st = 64; st > 0; st >>= 1) { if (tid < st) red[tid] += red[tid + st]; __syncthreads(); }
    float inv = 1.0f / red[0];
    __syncthreads();

    float acc = 0.f;
    for (int t0 = 0; t0 < TT; t0 += 128) {
        for (int r = r0; r < 128; r += 2)
            tile[r * 65 + c] = v[((long)(b * TT + t0 + r)) * DD + h * DH + c];
        __syncthreads();
        for (int r = r0; r < 128; r += 2)
            acc += sc[t0 + r] * tile[r * 65 + c];
        __syncthreads();
    }
    red[tid] = acc; __syncthreads();
    if (tid < 64) {
        float o = (red[tid] + red[tid + 64]) * inv;
        __nv_bfloat16 hh, ll;
        split_bf16(o, hh, ll);
        long idx = ((long)(b * TT + s)) * DD + h * DH + tid;
        oh[idx] = hh; ol[idx] = ll;
    }
}

// ---------------- host orchestration ----------------
static void run_gemm(const __nv_bfloat16* Ah, const __nv_bfloat16* Al,
                     const __nv_bfloat16* Wh, const __nv_bfloat16* Wl,
                     const float* bias, const float* res, float* Cf,
                     __nv_bfloat16* Csh, __nv_bfloat16* Csl,
                     int M, int N, int Ws, int K, int act) {
    dim3 grid(M / 128, (N + 127) / 128);
    gemm_tc<<<grid, 256, SMEM_BYTES>>>(Ah, Al, Wh, Wl, bias, res, Cf, Csh, Csl,
                                       M, N, Ws, K, act);
}

extern "C" void kernel_launch(void* const* d_in, const int* in_sizes, int n_in,
                              void* d_out, int out_size) {
    const int*   x       = (const int*)  d_in[0];
    const float* tok_emb = (const float*)d_in[1];
    const float* pos_emb = (const float*)d_in[2];
    const float* ln1_g   = (const float*)d_in[3];
    const float* ln1_b   = (const float*)d_in[4];
    const float* qkv_w   = (const float*)d_in[5];
    const float* qkv_b   = (const float*)d_in[6];
    const float* out_w   = (const float*)d_in[7];
    const float* out_b   = (const float*)d_in[8];
    const float* ln2_g   = (const float*)d_in[9];
    const float* ln2_b   = (const float*)d_in[10];
    const float* wi_w    = (const float*)d_in[11];
    const float* wi_b    = (const float*)d_in[12];
    const float* wo_w    = (const float*)d_in[13];
    const float* wo_b    = (const float*)d_in[14];
    const float* ln_g    = (const float*)d_in[15];
    const float* ln_b    = (const float*)d_in[16];
    const float* head_w  = (const float*)d_in[17];
    const float* head_b  = (const float*)d_in[18];
    float* logits = (float*)d_out;

    static bool attr_set = false;
    if (!attr_set) {
        cudaFuncSetAttribute(gemm_tc, cudaFuncAttributeMaxDynamicSharedMemorySize, SMEM_BYTES);
        attr_set = true;
    }

    float *h, *qkv;
    cudaGetSymbolAddress((void**)&h,   g_h);
    cudaGetSymbolAddress((void**)&qkv, g_qkv);
    __nv_bfloat16 *lnh, *lnl, *ath, *atl, *mlph, *mlpl;
    cudaGetSymbolAddress((void**)&lnh,  g_lnh);
    cudaGetSymbolAddress((void**)&lnl,  g_lnl);
    cudaGetSymbolAddress((void**)&ath,  g_ath);
    cudaGetSymbolAddress((void**)&atl,  g_atl);
    cudaGetSymbolAddress((void**)&mlph, g_mlph);
    cudaGetSymbolAddress((void**)&mlpl, g_mlpl);
    __nv_bfloat16 *qkvwh, *qkvwl, *outwh, *outwl, *wiwh, *wiwl, *wowh, *wowl, *headwh, *headwl;
    cudaGetSymbolAddress((void**)&qkvwh, g_qkvwh);
    cudaGetSymbolAddress((void**)&qkvwl, g_qkvwl);
    cudaGetSymbolAddress((void**)&outwh, g_outwh);
    cudaGetSymbolAddress((void**)&outwl, g_outwl);
    cudaGetSymbolAddress((void**)&wiwh,  g_wiwh);
    cudaGetSymbolAddress((void**)&wiwl,  g_wiwl);
    cudaGetSymbolAddress((void**)&wowh,  g_wowh);
    cudaGetSymbolAddress((void**)&wowl,  g_wowl);
    cudaGetSymbolAddress((void**)&headwh, g_headwh);
    cudaGetSymbolAddress((void**)&headwl, g_headwl);

    // split all weights (bandwidth-bound, ~150us total)
    split_w_kernel<<<2048, 256>>>(qkv_w, qkvwh, qkvwl, (long)LL*DD, 3*DD, 3*DD);
    split_w_kernel<<<1024, 256>>>(out_w, outwh, outwl, (long)LL*DD, DD, DD);
    split_w_kernel<<<2048, 256>>>(wi_w,  wiwh,  wiwl,  (long)LL*DD, MM, MM);
    split_w_kernel<<<2048, 256>>>(wo_w,  wowh,  wowl,  (long)LL*MM, DD, DD);
    split_w_kernel<<<4096, 256>>>(head_w, headwh, headwl, (long)DD, VV, VP);

    embed_kernel<<<(BTD + 255) / 256, 256>>>(x, tok_emb, pos_emb);

    for (int l = 0; l < LL; l++) {
        // attn block
        ln_kernel<<<BT, 256>>>(h, ln1_g + l * DD, ln1_b + l * DD, lnh, lnl);
        run_gemm(lnh, lnl, qkvwh + (long)l * DD * 3 * DD, qkvwl + (long)l * DD * 3 * DD,
                 qkv_b + l * 3 * DD, nullptr, qkv, nullptr, nullptr,
                 BT, 3 * DD, 3 * DD, DD, 0);
        attn_kernel<<<BB * HH * TT, 128>>>(qkv, ath, atl);
        run_gemm(ath, atl, outwh + (long)l * DD * DD, outwl + (long)l * DD * DD,
                 out_b + l * DD, h, h, nullptr, nullptr,
                 BT, DD, DD, DD, 0);            // h = h + attn@W + b

        // mlp block
        ln_kernel<<<BT, 256>>>(h, ln2_g + l * DD, ln2_b + l * DD, lnh, lnl);
        run_gemm(lnh, lnl, wiwh + (long)l * DD * MM, wiwl + (long)l * DD * MM,
                 wi_b + l * MM, nullptr, nullptr, mlph, mlpl,
                 BT, MM, MM, DD, 1);            // GELU -> bf16 split
        run_gemm(mlph, mlpl, wowh + (long)l * MM * DD, wowl + (long)l * MM * DD,
                 wo_b + l * DD, h, h, nullptr, nullptr,
                 BT, DD, DD, MM, 0);            // h = h + mlp@W + b
    }

    // final LN + head
    ln_kernel<<<BT, 256>>>(h, ln_g, ln_b, lnh, lnl);
    run_gemm(lnh, lnl, headwh, headwl, head_b, nullptr, logits, nullptr, nullptr,
             BT, VV, VP, DD, 0);
}

// round 5
// speedup vs baseline: 4.1854x; 2.7664x over previous
#include <cuda_runtime.h>
#include <cuda_bf16.h>
#include <math.h>
#include <stdint.h>

// Problem constants
#define BB 2
#define TT 1024
#define DD 1024
#define HH 16
#define DH 64
#define MM 4096
#define VV 50257
#define VP 50304           // VV padded to multiple of 128
#define LL 4
#define BT (BB*TT)          // 2048
#define BTD (BB*TT*DD)      // 2097152

// ---------------- scratch (device globals, no runtime alloc) ----------------
__device__ float g_h[BTD];
__device__ float g_qkv[3*BTD];

__device__ __nv_bfloat16 g_lnh[BTD],  g_lnl[BTD];
__device__ __nv_bfloat16 g_ath[BTD],  g_atl[BTD];
__device__ __nv_bfloat16 g_mlph[(long)BT*MM], g_mlpl[(long)BT*MM];

// split weights (hi/lo)
__device__ __nv_bfloat16 g_qkvwh[(long)LL*DD*3*DD], g_qkvwl[(long)LL*DD*3*DD];
__device__ __nv_bfloat16 g_outwh[(long)LL*DD*DD],   g_outwl[(long)LL*DD*DD];
__device__ __nv_bfloat16 g_wiwh[(long)LL*DD*MM],    g_wiwl[(long)LL*DD*MM];
__device__ __nv_bfloat16 g_wowh[(long)LL*MM*DD],    g_wowl[(long)LL*MM*DD];
__device__ __nv_bfloat16 g_headwh[(long)DD*VP],     g_headwl[(long)DD*VP];

// ---------------- helpers ----------------
__device__ __forceinline__ uint32_t smem_u32(const void* p) {
    return (uint32_t)__cvta_generic_to_shared(p);
}
__device__ __forceinline__ void cp16(void* dst, const void* src) {
    asm volatile("cp.async.ca.shared.global [%0], [%1], 16;\n"
                 :: "r"(smem_u32(dst)), "l"(src));
}
__device__ __forceinline__ void cp_commit() { asm volatile("cp.async.commit_group;\n"); }
__device__ __forceinline__ void cp_wait0()  { asm volatile("cp.async.wait_group 0;\n"); }
__device__ __forceinline__ void cp_wait1()  { asm volatile("cp.async.wait_group 1;\n"); }

__device__ __forceinline__ void ldsm_x4(uint32_t& r0, uint32_t& r1, uint32_t& r2, uint32_t& r3, uint32_t a) {
    asm volatile("ldmatrix.sync.aligned.m8n8.x4.shared.b16 {%0,%1,%2,%3}, [%4];\n"
                 : "=r"(r0), "=r"(r1), "=r"(r2), "=r"(r3) : "r"(a));
}
__device__ __forceinline__ void ldsm_x4_t(uint32_t& r0, uint32_t& r1, uint32_t& r2, uint32_t& r3, uint32_t a) {
    asm volatile("ldmatrix.sync.aligned.m8n8.x4.trans.shared.b16 {%0,%1,%2,%3}, [%4];\n"
                 : "=r"(r0), "=r"(r1), "=r"(r2), "=r"(r3) : "r"(a));
}
__device__ __forceinline__ void mma_bf16(float* c,
        uint32_t a0, uint32_t a1, uint32_t a2, uint32_t a3,
        uint32_t b0, uint32_t b1) {
    asm volatile("mma.sync.aligned.m16n8k16.row.col.f32.bf16.bf16.f32 "
                 "{%0,%1,%2,%3}, {%4,%5,%6,%7}, {%8,%9}, {%0,%1,%2,%3};\n"
                 : "+f"(c[0]), "+f"(c[1]), "+f"(c[2]), "+f"(c[3])
                 : "r"(a0), "r"(a1), "r"(a2), "r"(a3), "r"(b0), "r"(b1));
}
__device__ __forceinline__ void split_bf16(float f, __nv_bfloat16& h, __nv_bfloat16& l) {
    h = __float2bfloat16(f);
    l = __float2bfloat16(f - __bfloat162float(h));
}

// ---------------- weight splitter ----------------
__global__ void split_w_kernel(const float* __restrict__ W,
                               __nv_bfloat16* __restrict__ Wh,
                               __nv_bfloat16* __restrict__ Wl,
                               long rows, long N, long Ws) {
    long total = rows * Ws;
    for (long i = (long)blockIdx.x * blockDim.x + threadIdx.x; i < total;
         i += (long)gridDim.x * blockDim.x) {
        long r = i / Ws, c = i - r * Ws;
        float f = (c < N) ? W[r * N + c] : 0.f;
        __nv_bfloat16 h, l;
        split_bf16(f, h, l);
        Wh[i] = h; Wl[i] = l;
    }
}

// ---------------- embedding ----------------
__global__ void embed_kernel(const int* __restrict__ x,
                             const float* __restrict__ tok,
                             const float* __restrict__ pos) {
    int i = blockIdx.x * blockDim.x + threadIdx.x;
    if (i >= BTD) return;
    int d  = i % DD;
    int bt = i / DD;
    int t  = bt % TT;
    g_h[i] = tok[(long)x[bt] * DD + d] + pos[t * DD + d];
}

// ---------------- layernorm -> bf16 hi/lo ----------------
__global__ void ln_kernel(const float* __restrict__ x,
                          const float* __restrict__ g,
                          const float* __restrict__ b,
                          __nv_bfloat16* __restrict__ yh,
                          __nv_bfloat16* __restrict__ yl) {
    __shared__ float red[256];
    int row = blockIdx.x;
    const float* xr = x + (long)row * DD;
    int tid = threadIdx.x;

    float s = 0.f;
    for (int i = tid; i < DD; i += 256) s += xr[i];
    red[tid] = s; __syncthreads();
    for (int st = 128; st > 0; st >>= 1) { if (tid < st) red[tid] += red[tid + st]; __syncthreads(); }
    float mu = red[0] * (1.0f / DD);
    __syncthreads();

    float v = 0.f;
    for (int i = tid; i < DD; i += 256) { float d = xr[i] - mu; v += d * d; }
    red[tid] = v; __syncthreads();
    for (int st = 128; st > 0; st >>= 1) { if (tid < st) red[tid] += red[tid + st]; __syncthreads(); }
    float rstd = rsqrtf(red[0] * (1.0f / DD) + 1e-5f);

    for (int i = tid; i < DD; i += 256) {
        float y = (xr[i] - mu) * rstd * g[i] + b[i];
        __nv_bfloat16 h, l;
        split_bf16(y, h, l);
        long idx = (long)row * DD + i;
        yh[idx] = h; yl[idx] = l;
    }
}

// ---------------- GEMM (bf16x3, pre-split operands, cp.async double buffer) ----------------
#define AKS 40
#define BNS 136
#define STG_A (128*AKS)
#define STG_B (32*BNS)
#define STG_ELEMS (2*STG_A + 2*STG_B)
#define SMEM_BYTES (2 * STG_ELEMS * 2)

struct Stage {
    __nv_bfloat16 *Ah, *Al, *Bh, *Bl;
};
__device__ __forceinline__ Stage stage_ptrs(__nv_bfloat16* smem, int st) {
    __nv_bfloat16* base = smem + st * STG_ELEMS;
    Stage s;
    s.Ah = base;
    s.Al = base + STG_A;
    s.Bh = base + 2 * STG_A;
    s.Bl = base + 2 * STG_A + STG_B;
    return s;
}

__device__ __forceinline__ void load_stage(Stage s, int tid,
        const __nv_bfloat16* __restrict__ Agh, const __nv_bfloat16* __restrict__ Agl,
        const __nv_bfloat16* __restrict__ Wh,  const __nv_bfloat16* __restrict__ Wl,
        int m0, int n0, int k0, int K, int Ws) {
    #pragma unroll
    for (int p = 0; p < 2; p++) {
        int idx = p * 256 + tid;
        int ar = idx >> 2, ac = (idx & 3) * 8;
        long aoff = (long)(m0 + ar) * K + k0 + ac;
        cp16(&s.Ah[ar * AKS + ac], Agh + aoff);
        cp16(&s.Al[ar * AKS + ac], Agl + aoff);
        int br = idx >> 4, bc = (idx & 15) * 8;
        long boff = (long)(k0 + br) * Ws + n0 + bc;
        cp16(&s.Bh[br * BNS + bc], Wh + boff);
        cp16(&s.Bl[br * BNS + bc], Wl + boff);
    }
}

__global__ __launch_bounds__(256)
void gemm_tc(const __nv_bfloat16* __restrict__ Agh, const __nv_bfloat16* __restrict__ Agl,
             const __nv_bfloat16* __restrict__ Wh,  const __nv_bfloat16* __restrict__ Wl,
             const float* __restrict__ bias, const float* __restrict__ res,
             float* __restrict__ Cf,
             __nv_bfloat16* __restrict__ Csh, __nv_bfloat16* __restrict__ Csl,
             int M, int N, int Ws, int K, int act)
{
    extern __shared__ __nv_bfloat16 smem[];

    int tid  = threadIdx.x;
    int m0   = blockIdx.x * 128;
    int n0   = blockIdx.y * 128;
    int warp = tid >> 5, lane = tid & 31;
    int wm0  = (warp >> 1) * 32;
    int wn0  = (warp & 1) * 64;
    int gid  = lane >> 2, tig = lane & 3;

    float acc[2][8][4];
    #pragma unroll
    for (int i = 0; i < 2; i++)
        #pragma unroll
        for (int j = 0; j < 8; j++)
            #pragma unroll
            for (int q = 0; q < 4; q++) acc[i][j][q] = 0.f;

    int nkt = K >> 5;

    load_stage(stage_ptrs(smem, 0), tid, Agh, Agl, Wh, Wl, m0, n0, 0, K, Ws);
    cp_commit();

    for (int kt = 0; kt < nkt; kt++) {
        if (kt + 1 < nkt) {
            load_stage(stage_ptrs(smem, (kt + 1) & 1), tid, Agh, Agl, Wh, Wl,
                       m0, n0, (kt + 1) << 5, K, Ws);
            cp_commit();
            cp_wait1();
        } else {
            cp_wait0();
        }
        __syncthreads();

        Stage s = stage_ptrs(smem, kt & 1);
        #pragma unroll
        for (int kk = 0; kk < 32; kk += 16) {
            uint32_t ah[2][4], al[2][4], bh[8][2], bl[8][2];
            #pragma unroll
            for (int mc = 0; mc < 2; mc++) {
                int r = wm0 + mc * 16 + (lane & 15);
                int c = kk + ((lane >> 4) << 3);
                ldsm_x4(ah[mc][0], ah[mc][1], ah[mc][2], ah[mc][3], smem_u32(&s.Ah[r * AKS + c]));
                ldsm_x4(al[mc][0], al[mc][1], al[mc][2], al[mc][3], smem_u32(&s.Al[r * AKS + c]));
            }
            #pragma unroll
            for (int pc = 0; pc < 4; pc++) {
                int r = kk + (lane & 15);
                int c = wn0 + pc * 16 + ((lane >> 4) << 3);
                ldsm_x4_t(bh[2*pc][0], bh[2*pc][1], bh[2*pc+1][0], bh[2*pc+1][1], smem_u32(&s.Bh[r * BNS + c]));
                ldsm_x4_t(bl[2*pc][0], bl[2*pc][1], bl[2*pc+1][0], bl[2*pc+1][1], smem_u32(&s.Bl[r * BNS + c]));
            }
            #pragma unroll
            for (int mc = 0; mc < 2; mc++)
                #pragma unroll
                for (int ch = 0; ch < 8; ch++) {
                    mma_bf16(acc[mc][ch], ah[mc][0], ah[mc][1], ah[mc][2], ah[mc][3], bh[ch][0], bh[ch][1]);
                    mma_bf16(acc[mc][ch], ah[mc][0], ah[mc][1], ah[mc][2], ah[mc][3], bl[ch][0], bl[ch][1]);
                    mma_bf16(acc[mc][ch], al[mc][0], al[mc][1], al[mc][2], al[mc][3], bh[ch][0], bh[ch][1]);
                }
        }
        __syncthreads();
    }

    #pragma unroll
    for (int mc = 0; mc < 2; mc++) {
        #pragma unroll
        for (int ch = 0; ch < 8; ch++) {
            int n = n0 + wn0 + (ch >> 1) * 16 + (ch & 1) * 8 + tig * 2;
            #pragma unroll
            for (int h2 = 0; h2 < 2; h2++) {
                int m = m0 + wm0 + mc * 16 + gid + h2 * 8;
                #pragma unroll
                for (int j = 0; j < 2; j++) {
                    int nn = n + j;
                    if (nn < N) {
                        float v = acc[mc][ch][h2 * 2 + j] + bias[nn];
                        if (act == 1) v = 0.5f * v * (1.0f + erff(v * 0.70710678118654752f));
                        long idx = (long)m * N + nn;
                        if (res) v += res[idx];
                        if (Cf) Cf[idx] = v;
                        if (Csh) {
                            __nv_bfloat16 hh, ll;
                            split_bf16(v, hh, ll);
                            Csh[idx] = hh; Csl[idx] = ll;
                        }
                    }
                }
            }
        }
    }
}

// ---------------- flash attention: 128 queries per block, online softmax ----------------
// grid = BB*HH*(TT/128) = 256 blocks, 256 threads.
// smem (fp32, stride 65): Q[128][65] | K[64][65] | V[64][65] | P[128][65]  ~100KB
#define AT_SMEM ((128*65 + 64*65 + 64*65 + 128*65) * 4)

__global__ __launch_bounds__(256)
void attn_flash(const float* __restrict__ qkv,
                __nv_bfloat16* __restrict__ oh, __nv_bfloat16* __restrict__ ol) {
    extern __shared__ float sm[];
    float* Qs = sm;                    // 128*65
    float* Ks = Qs + 128 * 65;         // 64*65
    float* Vs = Ks + 64 * 65;          // 64*65
    float* Ps = Vs + 64 * 65;          // 128*65

    int blk = blockIdx.x;
    int qb = blk & 7;          // query block (TT/128 = 8)
    int bh = blk >> 3;
    int h  = bh % HH;
    int b  = bh / HH;

    const float* qg = qkv + ((long)(b * TT + qb * 128)) * DD + h * DH;
    const float* kg = qkv + BTD     + ((long)(b * TT)) * DD + h * DH;
    const float* vg = qkv + 2 * BTD + ((long)(b * TT)) * DD + h * DH;

    int tid = threadIdx.x;

    // load Q block
    for (int i = tid; i < 128 * 64; i += 256) {
        int r = i >> 6, c = i & 63;
        Qs[r * 65 + c] = qg[(long)r * DD + c];
    }
    __syncthreads();

    int qr = tid >> 1;         // query row 0..127
    int half = tid & 1;        // k/d half
    int kb = half * 32;

    float m = -1e30f, l = 0.f;
    float O[32];
    #pragma unroll
    for (int d = 0; d < 32; d++) O[d] = 0.f;

    for (int t0 = 0; t0 < TT; t0 += 64) {
        // load K/V chunk
        for (int i = tid; i < 64 * 64; i += 256) {
            int r = i >> 6, c = i & 63;
            Ks[r * 65 + c] = kg[(long)(t0 + r) * DD + c];
            Vs[r * 65 + c] = vg[(long)(t0 + r) * DD + c];
        }
        __syncthreads();

        // scores for this thread's 32 keys
        float s[32];
        float cmax = -1e30f;
        #pragma unroll
        for (int kk = 0; kk < 32; kk++) {
            float dot = 0.f;
            #pragma unroll
            for (int d = 0; d < 64; d++)
                dot += Qs[qr * 65 + d] * Ks[(kb + kk) * 65 + d];
            s[kk] = dot * 0.125f;
            cmax = fmaxf(cmax, s[kk]);
        }
        cmax = fmaxf(cmax, __shfl_xor_sync(0xffffffff, cmax, 1));
        float mnew = fmaxf(m, cmax);
        float corr = __expf(m - mnew);

        float lsum = 0.f;
        #pragma unroll
        for (int kk = 0; kk < 32; kk++) {
            float p = __expf(s[kk] - mnew);
            Ps[qr * 65 + kb + kk] = p;
            lsum += p;
        }
        lsum += __shfl_xor_sync(0xffffffff, lsum, 1);
        l = l * corr + lsum;
        #pragma unroll
        for (int d = 0; d < 32; d++) O[d] *= corr;
        m = mnew;
        __syncwarp();   // partner's P writes (same warp)

        // O += P @ V
        #pragma unroll 4
        for (int kk = 0; kk < 64; kk++) {
            float p = Ps[qr * 65 + kk];
            #pragma unroll
            for (int d = 0; d < 32; d++)
                O[d] += p * Vs[kk * 65 + kb + d];
        }
        __syncthreads();  // before next chunk overwrites K/V
    }

    float inv = 1.0f / l;
    long obase = ((long)(b * TT + qb * 128 + qr)) * DD + h * DH + kb;
    #pragma unroll
    for (int d = 0; d < 32; d++) {
        float o = O[d] * inv;
        __nv_bfloat16 hh, ll;
        split_bf16(o, hh, ll);
        oh[obase + d] = hh;
        ol[obase + d] = ll;
    }
}

// ---------------- host orchestration ----------------
static void run_gemm(const __nv_bfloat16* Ah, const __nv_bfloat16* Al,
                     const __nv_bfloat16* Wh, const __nv_bfloat16* Wl,
                     const float* bias, const float* res, float* Cf,
                     __nv_bfloat16* Csh, __nv_bfloat16* Csl,
                     int M, int N, int Ws, int K, int act) {
    dim3 grid(M / 128, (N + 127) / 128);
    gemm_tc<<<grid, 256, SMEM_BYTES>>>(Ah, Al, Wh, Wl, bias, res, Cf, Csh, Csl,
                                       M, N, Ws, K, act);
}

extern "C" void kernel_launch(void* const* d_in, const int* in_sizes, int n_in,
                              void* d_out, int out_size) {
    const int*   x       = (const int*)  d_in[0];
    const float* tok_emb = (const float*)d_in[1];
    const float* pos_emb = (const float*)d_in[2];
    const float* ln1_g   = (const float*)d_in[3];
    const float* ln1_b   = (const float*)d_in[4];
    const float* qkv_w   = (const float*)d_in[5];
    const float* qkv_b   = (const float*)d_in[6];
    const float* out_w   = (const float*)d_in[7];
    const float* out_b   = (const float*)d_in[8];
    const float* ln2_g   = (const float*)d_in[9];
    const float* ln2_b   = (const float*)d_in[10];
    const float* wi_w    = (const float*)d_in[11];
    const float* wi_b    = (const float*)d_in[12];
    const float* wo_w    = (const float*)d_in[13];
    const float* wo_b    = (const float*)d_in[14];
    const float* ln_g    = (const float*)d_in[15];
    const float* ln_b    = (const float*)d_in[16];
    const float* head_w  = (const float*)d_in[17];
    const float* head_b  = (const float*)d_in[18];
    float* logits = (float*)d_out;

    static bool attr_set = false;
    if (!attr_set) {
        cudaFuncSetAttribute(gemm_tc, cudaFuncAttributeMaxDynamicSharedMemorySize, SMEM_BYTES);
        cudaFuncSetAttribute(attn_flash, cudaFuncAttributeMaxDynamicSharedMemorySize, AT_SMEM);
        attr_set = true;
    }

    float *h, *qkv;
    cudaGetSymbolAddress((void**)&h,   g_h);
    cudaGetSymbolAddress((void**)&qkv, g_qkv);
    __nv_bfloat16 *lnh, *lnl, *ath, *atl, *mlph, *mlpl;
    cudaGetSymbolAddress((void**)&lnh,  g_lnh);
    cudaGetSymbolAddress((void**)&lnl,  g_lnl);
    cudaGetSymbolAddress((void**)&ath,  g_ath);
    cudaGetSymbolAddress((void**)&atl,  g_atl);
    cudaGetSymbolAddress((void**)&mlph, g_mlph);
    cudaGetSymbolAddress((void**)&mlpl, g_mlpl);
    __nv_bfloat16 *qkvwh, *qkvwl, *outwh, *outwl, *wiwh, *wiwl, *wowh, *wowl, *headwh, *headwl;
    cudaGetSymbolAddress((void**)&qkvwh, g_qkvwh);
    cudaGetSymbolAddress((void**)&qkvwl, g_qkvwl);
    cudaGetSymbolAddress((void**)&outwh, g_outwh);
    cudaGetSymbolAddress((void**)&outwl, g_outwl);
    cudaGetSymbolAddress((void**)&wiwh,  g_wiwh);
    cudaGetSymbolAddress((void**)&wiwl,  g_wiwl);
    cudaGetSymbolAddress((void**)&wowh,  g_wowh);
    cudaGetSymbolAddress((void**)&wowl,  g_wowl);
    cudaGetSymbolAddress((void**)&headwh, g_headwh);
    cudaGetSymbolAddress((void**)&headwl, g_headwl);

    // split all weights
    split_w_kernel<<<2048, 256>>>(qkv_w, qkvwh, qkvwl, (long)LL*DD, 3*DD, 3*DD);
    split_w_kernel<<<1024, 256>>>(out_w, outwh, outwl, (long)LL*DD, DD, DD);
    split_w_kernel<<<2048, 256>>>(wi_w,  wiwh,  wiwl,  (long)LL*DD, MM, MM);
    split_w_kernel<<<2048, 256>>>(wo_w,  wowh,  wowl,  (long)LL*MM, DD, DD);
    split_w_kernel<<<4096, 256>>>(head_w, headwh, headwl, (long)DD, VV, VP);

    embed_kernel<<<(BTD + 255) / 256, 256>>>(x, tok_emb, pos_emb);

    for (int l = 0; l < LL; l++) {
        ln_kernel<<<BT, 256>>>(h, ln1_g + l * DD, ln1_b + l * DD, lnh, lnl);
        run_gemm(lnh, lnl, qkvwh + (long)l * DD * 3 * DD, qkvwl + (long)l * DD * 3 * DD,
                 qkv_b + l * 3 * DD, nullptr, qkv, nullptr, nullptr,
                 BT, 3 * DD, 3 * DD, DD, 0);
        attn_flash<<<BB * HH * (TT / 128), 256, AT_SMEM>>>(qkv, ath, atl);
        run_gemm(ath, atl, outwh + (long)l * DD * DD, outwl + (long)l * DD * DD,
                 out_b + l * DD, h, h, nullptr, nullptr,
                 BT, DD, DD, DD, 0);

        ln_kernel<<<BT, 256>>>(h, ln2_g + l * DD, ln2_b + l * DD, lnh, lnl);
        run_gemm(lnh, lnl, wiwh + (long)l * DD * MM, wiwl + (long)l * DD * MM,
                 wi_b + l * MM, nullptr, nullptr, mlph, mlpl,
                 BT, MM, MM, DD, 1);
        run_gemm(mlph, mlpl, wowh + (long)l * MM * DD, wowl + (long)l * MM * DD,
                 wo_b + l * DD, h, h, nullptr, nullptr,
                 BT, DD, DD, MM, 0);
    }

    ln_kernel<<<BT, 256>>>(h, ln_g, ln_b, lnh, lnl);
    run_gemm(lnh, lnl, headwh, headwl, head_b, nullptr, logits, nullptr, nullptr,
             BT, VV, VP, DD, 0);
}